// round 1
// baseline (speedup 1.0000x reference)
#include <cuda_runtime.h>
#include <math.h>

// ---------------- problem constants ----------------
#define QN    2048
#define NP    32768
#define DM    256
#define KK    8
#define HN    8
#define HDN   64
#define STN   64
#define DINc  512
#define CONVc 640
#define NPROJc 1160
#define HIDc  1024

// ---------------- scratch (device globals; no allocation allowed) -------------
__device__ float g_qproj[QN * DM];
__device__ float g_kw[QN * KK];
__device__ int   g_knn[QN * KK];
__device__ float g_mixed[QN * DM];
__device__ float g_vm[QN * DM];
__device__ float g_w[QN * DM];
__device__ float g_tmp[QN * DM];
__device__ float g_x[QN * DM];
__device__ float g_xn[QN * DM];
__device__ int   g_inv[2 * QN];
__device__ float g_proj[2 * QN * NPROJc];
__device__ float g_xBC[2 * QN * CONVc];
__device__ float g_dt[2 * QN * HN];
__device__ float g_dA[2 * QN * HN];
__device__ float g_y[2 * QN * DINc];
__device__ float g_yout[2 * QN * DM];
__device__ float g_h1[QN * HIDc];
__device__ float g_h2[QN * DM];

// ---------------- helpers ----------------
__device__ __forceinline__ float blockSum256(float v) {
    __shared__ float sh[8];
    int lane = threadIdx.x & 31;
    int w    = threadIdx.x >> 5;
#pragma unroll
    for (int off = 16; off; off >>= 1) v += __shfl_xor_sync(0xffffffffu, v, off);
    if (lane == 0) sh[w] = v;
    __syncthreads();
    if (threadIdx.x == 0) {
        float s = sh[0] + sh[1] + sh[2] + sh[3] + sh[4] + sh[5] + sh[6] + sh[7];
        sh[0] = s;
    }
    __syncthreads();
    float r = sh[0];
    __syncthreads();
    return r;
}

__device__ __forceinline__ float siluf(float x) { return x / (1.0f + expf(-x)); }

// ---------------- generic fp32 GEMM: C[M,N] = A[M,K] @ B[N,K]^T ----------------
// BM=BN=64, BK=16, 256 threads, 4x4 microtile. Optional rowmap gathers A rows.
__global__ void gemm_rt(const float* __restrict__ A, const float* __restrict__ B,
                        float* __restrict__ C, int M, int N, int K,
                        const int* __restrict__ rowmap) {
    __shared__ float As[16][68];
    __shared__ float Bs[16][68];
    int tid = threadIdx.x;
    int tx = tid & 15, ty = tid >> 4;
    int mBase = blockIdx.y * 64, nBase = blockIdx.x * 64;

    int lm  = tid >> 2;          // 0..63
    int lk4 = (tid & 3) * 4;     // 0,4,8,12

    int arow = mBase + lm;
    int aidx = rowmap ? rowmap[arow] : arow;
    const float* Aptr = A + (size_t)aidx * K + lk4;
    int brow = nBase + lm;
    bool bvalid = (brow < N);
    const float* Bptr = B + (size_t)(bvalid ? brow : 0) * K + lk4;

    float acc[4][4];
#pragma unroll
    for (int i = 0; i < 4; i++)
#pragma unroll
        for (int j = 0; j < 4; j++) acc[i][j] = 0.0f;

    for (int k0 = 0; k0 < K; k0 += 16) {
        float4 av = *(const float4*)(Aptr + k0);
        float4 bv = bvalid ? *(const float4*)(Bptr + k0) : make_float4(0.f, 0.f, 0.f, 0.f);
        As[lk4 + 0][lm] = av.x; As[lk4 + 1][lm] = av.y;
        As[lk4 + 2][lm] = av.z; As[lk4 + 3][lm] = av.w;
        Bs[lk4 + 0][lm] = bv.x; Bs[lk4 + 1][lm] = bv.y;
        Bs[lk4 + 2][lm] = bv.z; Bs[lk4 + 3][lm] = bv.w;
        __syncthreads();
#pragma unroll
        for (int k = 0; k < 16; k++) {
            float4 a = *(const float4*)&As[k][ty * 4];
            float4 b = *(const float4*)&Bs[k][tx * 4];
            acc[0][0] += a.x * b.x; acc[0][1] += a.x * b.y; acc[0][2] += a.x * b.z; acc[0][3] += a.x * b.w;
            acc[1][0] += a.y * b.x; acc[1][1] += a.y * b.y; acc[1][2] += a.y * b.z; acc[1][3] += a.y * b.w;
            acc[2][0] += a.z * b.x; acc[2][1] += a.z * b.y; acc[2][2] += a.z * b.z; acc[2][3] += a.z * b.w;
            acc[3][0] += a.w * b.x; acc[3][1] += a.w * b.y; acc[3][2] += a.w * b.z; acc[3][3] += a.w * b.w;
        }
        __syncthreads();
    }
#pragma unroll
    for (int i = 0; i < 4; i++) {
        int row = mBase + ty * 4 + i;
#pragma unroll
        for (int j = 0; j < 4; j++) {
            int col = nBase + tx * 4 + j;
            if (col < N) C[(size_t)row * N + col] = acc[i][j];
        }
    }
}

// ---------------- inverse permutation ----------------
__global__ void inv_kernel(const int* __restrict__ order) {
    int i = blockIdx.x * blockDim.x + threadIdx.x;
    if (i < 2 * QN) {
        int b = i >> 11;
        int t = i & (QN - 1);
        g_inv[(b << 11) + order[i]] = t;
    }
}

// ---------------- KNN: 1 warp / query, smem coord tiles ----------------
__global__ void knn_kernel(const float* __restrict__ qpos, const float* __restrict__ spos) {
    __shared__ float tile[1024 * 3];
    __shared__ unsigned long long cand[8][256];
    int tid = threadIdx.x, lane = tid & 31, w = tid >> 5;
    int q = blockIdx.x * 8 + w;
    float qx = qpos[q * 3 + 0], qy = qpos[q * 3 + 1], qz = qpos[q * 3 + 2];
    float qq = qx * qx + qy * qy + qz * qz;

    float bd[8]; int bi[8];
#pragma unroll
    for (int j = 0; j < 8; j++) { bd[j] = 3.4e38f; bi[j] = 0; }

    for (int base = 0; base < NP; base += 1024) {
        __syncthreads();
        for (int i = tid; i < 3072; i += 256) tile[i] = spos[base * 3 + i];
        __syncthreads();
        for (int p = lane; p < 1024; p += 32) {
            float px = tile[3 * p], py = tile[3 * p + 1], pz = tile[3 * p + 2];
            float pp = px * px + py * py + pz * pz;
            float d2 = qq + pp - 2.0f * (qx * px + qy * py + qz * pz);
            if (d2 < bd[7]) {
                bd[7] = d2; bi[7] = base + p;
#pragma unroll
                for (int j = 7; j > 0; j--) {
                    if (bd[j] < bd[j - 1]) {
                        float td = bd[j]; bd[j] = bd[j - 1]; bd[j - 1] = td;
                        int ti = bi[j]; bi[j] = bi[j - 1]; bi[j - 1] = ti;
                    }
                }
            }
        }
    }
#pragma unroll
    for (int j = 0; j < 8; j++)
        cand[w][lane * 8 + j] =
            ((unsigned long long)__float_as_uint(fmaxf(bd[j], 0.0f)) << 32) | (unsigned)bi[j];

    int head = 0;
    for (int r = 0; r < 8; r++) {
        unsigned long long key = (head < 8) ? cand[w][lane * 8 + head] : 0xFFFFFFFFFFFFFFFFull;
        unsigned long long mn = key;
#pragma unroll
        for (int off = 16; off; off >>= 1) {
            unsigned long long o = __shfl_xor_sync(0xffffffffu, mn, off);
            if (o < mn) mn = o;
        }
        if (key == mn && head < 8) head++;
        if (lane == 0) g_knn[q * 8 + r] = (int)(mn & 0xFFFFFFFFull);
    }
}

// ---------------- kw = softmax(qproj @ w_k^T + w_b) ----------------
__global__ void kw_kernel(const float* __restrict__ wk, const float* __restrict__ wb) {
    int lane = threadIdx.x & 31, w = threadIdx.x >> 5;
    int q = blockIdx.x * 8 + w;
    float qv[8];
#pragma unroll
    for (int j = 0; j < 8; j++) qv[j] = g_qproj[q * DM + j * 32 + lane];
    float lg[8];
#pragma unroll
    for (int k = 0; k < 8; k++) {
        float p = 0.0f;
#pragma unroll
        for (int j = 0; j < 8; j++) p += qv[j] * wk[k * DM + j * 32 + lane];
#pragma unroll
        for (int off = 16; off; off >>= 1) p += __shfl_xor_sync(0xffffffffu, p, off);
        lg[k] = p + wb[k];
    }
    if (lane == 0) {
        float mx = lg[0];
#pragma unroll
        for (int k = 1; k < 8; k++) mx = fmaxf(mx, lg[k]);
        float s = 0.0f;
#pragma unroll
        for (int k = 0; k < 8; k++) { lg[k] = expf(lg[k] - mx); s += lg[k]; }
        float is = 1.0f / s;
#pragma unroll
        for (int k = 0; k < 8; k++) g_kw[q * 8 + k] = lg[k] * is;
    }
}

// ---------------- mixed = sum_k kw * feat[idx] ----------------
__global__ void mix_kernel(const float* __restrict__ feats) {
    int q = blockIdx.x, d = threadIdx.x;
    float acc = 0.0f;
#pragma unroll
    for (int k = 0; k < 8; k++)
        acc += g_kw[q * 8 + k] * feats[(size_t)g_knn[q * 8 + k] * DM + d];
    g_mixed[q * DM + d] = acc;
}

__global__ void ewmul_kernel() {
    int i = blockIdx.x * blockDim.x + threadIdx.x;
    g_w[i] = g_qproj[i] * g_vm[i];
}

// ---------------- LayerNorm variants ----------------
__global__ void ln_add_kernel(float* __restrict__ out, const float* __restrict__ a,
                              const float* __restrict__ b) {
    int row = blockIdx.x, d = threadIdx.x;
    float v = a[row * DM + d] + b[row * DM + d];
    float mean = blockSum256(v) * (1.0f / DM);
    float diff = v - mean;
    float var = blockSum256(diff * diff) * (1.0f / DM);
    out[row * DM + d] = diff * rsqrtf(var + 1e-5f);
}

__global__ void ln_plain_kernel(float* __restrict__ out, const float* __restrict__ a) {
    int row = blockIdx.x, d = threadIdx.x;
    float v = a[row * DM + d];
    float mean = blockSum256(v) * (1.0f / DM);
    float diff = v - mean;
    float var = blockSum256(diff * diff) * (1.0f / DM);
    out[row * DM + d] = diff * rsqrtf(var + 1e-5f);
}

// ---------------- conv1d + silu + dt/dA precompute ----------------
__global__ void conv_dt_kernel(const float* __restrict__ Wconv, const float* __restrict__ bconv,
                               const float* __restrict__ Alog, const float* __restrict__ dtb) {
    int bt = blockIdx.x;              // 0..4095
    int b = bt >> 11, t = bt & (QN - 1);
    for (int c = threadIdx.x; c < CONVc; c += blockDim.x) {
        float acc = bconv[c];
#pragma unroll
        for (int j = 0; j < 4; j++) {
            int tt = t - 3 + j;
            if (tt >= 0)
                acc += g_proj[(size_t)(b * QN + tt) * NPROJc + DINc + c] * Wconv[c * 4 + j];
        }
        g_xBC[(size_t)bt * CONVc + c] = siluf(acc);
    }
    if (threadIdx.x < HN) {
        int h = threadIdx.x;
        float draw = g_proj[(size_t)bt * NPROJc + DINc + CONVc + h] + dtb[h];
        float dt = (draw > 20.0f) ? draw : log1pf(expf(draw));
        float A = -expf(Alog[h]);
        g_dt[bt * HN + h] = dt;
        g_dA[bt * HN + h] = expf(dt * A);
    }
}

// ---------------- sequential SSM scan: 1 warp per (b,h,d) ----------------
__global__ void scan_kernel() {
    int gw = (blockIdx.x * blockDim.x + threadIdx.x) >> 5;
    int lane = threadIdx.x & 31;
    int b = gw >> 9;
    int h = (gw >> 6) & 7;
    int d = gw & 63;
    const float* xb = g_xBC + (size_t)b * QN * CONVc;
    const float* dtp = g_dt + b * QN * HN + h;
    const float* dAp = g_dA + b * QN * HN + h;
    float* yp = g_y + (size_t)b * QN * DINc + h * HDN + d;
    int xoff = h * HDN + d;

    float h0 = 0.0f, h1 = 0.0f;
    for (int t = 0; t < QN; t += 4) {
        float c[4];
#pragma unroll
        for (int u = 0; u < 4; u++) {
            const float* row = xb + (size_t)(t + u) * CONVc;
            float da = dAp[(t + u) * HN];
            float dx = dtp[(t + u) * HN] * row[xoff];
            h0 = h0 * da + dx * row[512 + lane];
            h1 = h1 * da + dx * row[544 + lane];
            c[u] = h0 * row[576 + lane] + h1 * row[608 + lane];
        }
#pragma unroll
        for (int off = 16; off; off >>= 1) {
#pragma unroll
            for (int u = 0; u < 4; u++) c[u] += __shfl_xor_sync(0xffffffffu, c[u], off);
        }
        float v = c[0];
        if (lane == 1) v = c[1];
        else if (lane == 2) v = c[2];
        else if (lane == 3) v = c[3];
        if (lane < 4) yp[(size_t)(t + lane) * DINc] = v;
    }
}

// ---------------- gated RMSNorm: y = rms((y + D*x) * silu(z)) * rmsw ----------------
__global__ void gated_rms_kernel(const float* __restrict__ Dv, const float* __restrict__ rmsw) {
    int bt = blockIdx.x;
    int i0 = threadIdx.x, i1 = threadIdx.x + 256;
    float ga, gb;
    {
        int h = i0 >> 6;
        float yy = g_y[(size_t)bt * DINc + i0] + Dv[h] * g_xBC[(size_t)bt * CONVc + i0];
        float z = g_proj[(size_t)bt * NPROJc + i0];
        ga = yy * siluf(z);
    }
    {
        int h = i1 >> 6;
        float yy = g_y[(size_t)bt * DINc + i1] + Dv[h] * g_xBC[(size_t)bt * CONVc + i1];
        float z = g_proj[(size_t)bt * NPROJc + i1];
        gb = yy * siluf(z);
    }
    float ss = blockSum256(ga * ga + gb * gb);
    float r = rsqrtf(ss * (1.0f / DINc) + 1e-5f);
    g_y[(size_t)bt * DINc + i0] = ga * r * rmsw[i0];
    g_y[(size_t)bt * DINc + i1] = gb * r * rmsw[i1];
}

// ---------------- unsort + mean(paths) + residual + LN ----------------
__global__ void combine_ln_kernel() {
    int qi = blockIdx.x, d = threadIdx.x;
    int p0 = g_inv[qi];
    int p1 = g_inv[QN + qi];
    float v = g_x[qi * DM + d] +
              0.5f * (g_yout[(size_t)p0 * DM + d] + g_yout[(size_t)(QN + p1) * DM + d]);
    float mean = blockSum256(v) * (1.0f / DM);
    float diff = v - mean;
    float var = blockSum256(diff * diff) * (1.0f / DM);
    g_x[qi * DM + d] = diff * rsqrtf(var + 1e-5f);
}

// ---------------- FFN elementwise ----------------
__global__ void gelu_bias_kernel(const float* __restrict__ b1) {
    int i = blockIdx.x * blockDim.x + threadIdx.x;
    float v = g_h1[i] + b1[i & (HIDc - 1)];
    g_h1[i] = 0.5f * v * (1.0f + erff(v * 0.70710678118654752f));
}

__global__ void final_ln_kernel(float* __restrict__ out, const float* __restrict__ b2) {
    int row = blockIdx.x, d = threadIdx.x;
    float v = g_x[row * DM + d] + g_h2[row * DM + d] + b2[d];
    float mean = blockSum256(v) * (1.0f / DM);
    float diff = v - mean;
    float var = blockSum256(diff * diff) * (1.0f / DM);
    out[row * DM + d] = diff * rsqrtf(var + 1e-5f);
}

// ---------------- host launcher ----------------
static float* symf(const void* p) { return (float*)p; }

extern "C" void kernel_launch(void* const* d_in, const int* in_sizes, int n_in,
                              void* d_out, int out_size) {
    (void)in_sizes; (void)n_in; (void)out_size;
    const float* query     = (const float*)d_in[0];
    const float* query_pos = (const float*)d_in[1];
    const float* inst_feats= (const float*)d_in[2];
    const float* sp_coords = (const float*)d_in[3];
    const float* w_q = (const float*)d_in[4];
    const float* w_v = (const float*)d_in[5];
    const float* w_o = (const float*)d_in[6];
    const float* w_k = (const float*)d_in[7];
    const float* w_b = (const float*)d_in[8];
    const float* ssm_Win   = (const float*)d_in[9];
    const float* ssm_Wconv = (const float*)d_in[10];
    const float* ssm_bconv = (const float*)d_in[11];
    const float* ssm_Alog  = (const float*)d_in[12];
    const float* ssm_D     = (const float*)d_in[13];
    const float* ssm_dtb   = (const float*)d_in[14];
    const float* ssm_rmsw  = (const float*)d_in[15];
    const float* ssm_Wout  = (const float*)d_in[16];
    const float* ffn_w1 = (const float*)d_in[17];
    const float* ffn_b1 = (const float*)d_in[18];
    const float* ffn_w2 = (const float*)d_in[19];
    const float* ffn_b2 = (const float*)d_in[20];
    const int*   order  = (const int*)d_in[21];
    float* out = (float*)d_out;

    // device-global buffer addresses for the generic GEMM
    void *p_qproj, *p_mixed, *p_vm, *p_w, *p_tmp, *p_x, *p_xn, *p_proj, *p_y, *p_yout, *p_h1, *p_h2;
    cudaGetSymbolAddress(&p_qproj, g_qproj);
    cudaGetSymbolAddress(&p_mixed, g_mixed);
    cudaGetSymbolAddress(&p_vm,    g_vm);
    cudaGetSymbolAddress(&p_w,     g_w);
    cudaGetSymbolAddress(&p_tmp,   g_tmp);
    cudaGetSymbolAddress(&p_x,     g_x);
    cudaGetSymbolAddress(&p_xn,    g_xn);
    cudaGetSymbolAddress(&p_proj,  g_proj);
    cudaGetSymbolAddress(&p_y,     g_y);
    cudaGetSymbolAddress(&p_yout,  g_yout);
    cudaGetSymbolAddress(&p_h1,    g_h1);
    cudaGetSymbolAddress(&p_h2,    g_h2);

    // --- front end ---
    inv_kernel<<<16, 256>>>(order);
    knn_kernel<<<QN / 8, 256>>>(query_pos, sp_coords);

    gemm_rt<<<dim3(DM / 64, QN / 64), 256>>>(query, w_q, symf(p_qproj), QN, DM, DM, nullptr);
    kw_kernel<<<QN / 8, 256>>>(w_k, w_b);
    mix_kernel<<<QN, 256>>>(inst_feats);
    gemm_rt<<<dim3(DM / 64, QN / 64), 256>>>(symf(p_mixed), w_v, symf(p_vm), QN, DM, DM, nullptr);
    ewmul_kernel<<<QN * DM / 256, 256>>>();
    gemm_rt<<<dim3(DM / 64, QN / 64), 256>>>(symf(p_w), w_o, symf(p_tmp), QN, DM, DM, nullptr);
    ln_add_kernel<<<QN, 256>>>(symf(p_x), symf(p_tmp), query);

    // --- SSM layers ---
    for (int l = 0; l < 2; l++) {
        const float* Win_l   = ssm_Win   + (size_t)l * NPROJc * DM;
        const float* Wconv_l = ssm_Wconv + (size_t)l * CONVc * 4;
        const float* bconv_l = ssm_bconv + (size_t)l * CONVc;
        const float* Alog_l  = ssm_Alog  + l * HN;
        const float* D_l     = ssm_D     + l * HN;
        const float* dtb_l   = ssm_dtb   + l * HN;
        const float* rmsw_l  = ssm_rmsw  + (size_t)l * DINc;
        const float* Wout_l  = ssm_Wout  + (size_t)l * DM * DINc;

        ln_plain_kernel<<<QN, 256>>>(symf(p_xn), symf(p_x));
        gemm_rt<<<dim3((NPROJc + 63) / 64, 2 * QN / 64), 256>>>(
            symf(p_xn), Win_l, symf(p_proj), 2 * QN, NPROJc, DM, order);
        conv_dt_kernel<<<2 * QN, 256>>>(Wconv_l, bconv_l, Alog_l, dtb_l);
        scan_kernel<<<128, 256>>>();
        gated_rms_kernel<<<2 * QN, 256>>>(D_l, rmsw_l);
        gemm_rt<<<dim3(DM / 64, 2 * QN / 64), 256>>>(
            symf(p_y), Wout_l, symf(p_yout), 2 * QN, DM, DINc, nullptr);
        combine_ln_kernel<<<QN, 256>>>();
    }

    // --- FFN ---
    gemm_rt<<<dim3(HIDc / 64, QN / 64), 256>>>(symf(p_x), ffn_w1, symf(p_h1), QN, HIDc, DM, nullptr);
    gelu_bias_kernel<<<QN * HIDc / 256, 256>>>(ffn_b1);
    gemm_rt<<<dim3(DM / 64, QN / 64), 256>>>(symf(p_h1), ffn_w2, symf(p_h2), QN, DM, HIDc, nullptr);
    final_ln_kernel<<<QN, 256>>>(out, ffn_b2);
}

// round 5
// speedup vs baseline: 1.4444x; 1.4444x over previous
#include <cuda_runtime.h>
#include <math.h>

// ---------------- problem constants ----------------
#define QN    2048
#define NP    32768
#define DM    256
#define KK    8
#define HN    8
#define HDN   64
#define STN   64
#define DINc  512
#define CONVc 640
#define NPROJc 1160
#define HIDc  1024

// ---------------- scratch (device globals; no allocation allowed) -------------
__device__ float g_qproj[QN * DM];
__device__ float g_kw[QN * KK];
__device__ int   g_knn[QN * KK];
__device__ float g_mixed[QN * DM];
__device__ float g_vm[QN * DM];
__device__ float g_w[QN * DM];
__device__ float g_tmp[QN * DM];
__device__ float g_x[QN * DM];
__device__ float g_xn[QN * DM];
__device__ int   g_inv[2 * QN];
__device__ float g_proj[2 * QN * NPROJc];
__device__ float g_xBC[2 * QN * CONVc];
__device__ float g_dt[2 * QN * HN];
__device__ float g_dA[2 * QN * HN];
__device__ float g_y[2 * QN * DINc];
__device__ float g_yout[2 * QN * DM];
__device__ float g_h1[QN * HIDc];
__device__ float g_h2[QN * DM];
__device__ float g_split[4 * QN * DM];   // split-K partials (covers 2*4096*256 too)

// ---------------- helpers ----------------
__device__ __forceinline__ float blockSum256(float v) {
    __shared__ float sh[8];
    int lane = threadIdx.x & 31;
    int w    = threadIdx.x >> 5;
#pragma unroll
    for (int off = 16; off; off >>= 1) v += __shfl_xor_sync(0xffffffffu, v, off);
    if (lane == 0) sh[w] = v;
    __syncthreads();
    if (threadIdx.x == 0) {
        float s = sh[0] + sh[1] + sh[2] + sh[3] + sh[4] + sh[5] + sh[6] + sh[7];
        sh[0] = s;
    }
    __syncthreads();
    float r = sh[0];
    __syncthreads();
    return r;
}

__device__ __forceinline__ float siluf(float x) { return x / (1.0f + expf(-x)); }

// ---------------- fp32 GEMM: C[M,N] = A[M,K] @ B[N,K]^T -----------------------
// 64x64 tile, BK=16, 64 threads, 8x8 microtile, register-staged prefetch.
// gridDim.z = split-K count; each z computes kLen columns starting z*kLen and
// writes to C + z*M*N (partials reduced later). rowmap optionally gathers A rows.
__global__ __launch_bounds__(64) void gemm64(
        const float* __restrict__ A, const float* __restrict__ B,
        float* __restrict__ C, int M, int N, int K, int kLen,
        const int* __restrict__ rowmap) {
    __shared__ float As[16][68];
    __shared__ float Bs[16][68];
    int tid = threadIdx.x;                 // 0..63
    int mBase = blockIdx.y * 64;
    int nBase = blockIdx.x * 64;
    int kStart = blockIdx.z * kLen;
    C += (size_t)blockIdx.z * M * N;

    int arow = mBase + tid;
    int aidx = rowmap ? rowmap[arow] : arow;
    const float* Aptr = A + (size_t)aidx * K + kStart;
    int brow = nBase + tid;
    bool bvalid = (brow < N);
    const float* Bptr = B + (size_t)(bvalid ? brow : 0) * K + kStart;

    int tx = (tid & 7) * 4;                // 0..28
    int ty = (tid >> 3) * 4;               // 0..28

    float acc[8][8];
#pragma unroll
    for (int i = 0; i < 8; i++)
#pragma unroll
        for (int j = 0; j < 8; j++) acc[i][j] = 0.0f;

    float4 pa[4], pb[4];
#pragma unroll
    for (int j = 0; j < 4; j++) {
        pa[j] = *(const float4*)(Aptr + j * 4);
        pb[j] = bvalid ? *(const float4*)(Bptr + j * 4) : make_float4(0.f, 0.f, 0.f, 0.f);
    }

    int kk = 0;
    while (true) {
        __syncthreads();
#pragma unroll
        for (int j = 0; j < 4; j++) {
            As[j * 4 + 0][tid] = pa[j].x; As[j * 4 + 1][tid] = pa[j].y;
            As[j * 4 + 2][tid] = pa[j].z; As[j * 4 + 3][tid] = pa[j].w;
            Bs[j * 4 + 0][tid] = pb[j].x; Bs[j * 4 + 1][tid] = pb[j].y;
            Bs[j * 4 + 2][tid] = pb[j].z; Bs[j * 4 + 3][tid] = pb[j].w;
        }
        __syncthreads();
        kk += 16;
        bool more = (kk < kLen);
        if (more) {
#pragma unroll
            for (int j = 0; j < 4; j++) {
                pa[j] = *(const float4*)(Aptr + kk + j * 4);
                pb[j] = bvalid ? *(const float4*)(Bptr + kk + j * 4)
                               : make_float4(0.f, 0.f, 0.f, 0.f);
            }
        }
#pragma unroll
        for (int k = 0; k < 16; k++) {
            float4 a0 = *(const float4*)&As[k][ty];
            float4 a1 = *(const float4*)&As[k][ty + 32];
            float4 b0 = *(const float4*)&Bs[k][tx];
            float4 b1 = *(const float4*)&Bs[k][tx + 32];
            float av[8] = {a0.x, a0.y, a0.z, a0.w, a1.x, a1.y, a1.z, a1.w};
            float bv[8] = {b0.x, b0.y, b0.z, b0.w, b1.x, b1.y, b1.z, b1.w};
#pragma unroll
            for (int i = 0; i < 8; i++)
#pragma unroll
                for (int j = 0; j < 8; j++) acc[i][j] += av[i] * bv[j];
        }
        if (!more) break;
    }

    bool c0ok = (nBase + tx + 3) < N;
    bool c1ok = (nBase + 32 + tx + 3) < N;
#pragma unroll
    for (int i = 0; i < 8; i++) {
        int row = mBase + ((i < 4) ? (ty + i) : (32 + ty + i - 4));
        if (c0ok) {
            float4 v = make_float4(acc[i][0], acc[i][1], acc[i][2], acc[i][3]);
            *(float4*)(C + (size_t)row * N + nBase + tx) = v;
        }
        if (c1ok) {
            float4 v = make_float4(acc[i][4], acc[i][5], acc[i][6], acc[i][7]);
            *(float4*)(C + (size_t)row * N + nBase + 32 + tx) = v;
        }
    }
}

// sum S split-K partials (deterministic order)
__global__ void reduce_split(float* __restrict__ dst, const float* __restrict__ src,
                             int MN, int S) {
    int i = blockIdx.x * blockDim.x + threadIdx.x;
    if (i < MN) {
        float s = 0.0f;
        for (int k = 0; k < S; k++) s += src[(size_t)k * MN + i];
        dst[i] = s;
    }
}

// ---------------- inverse permutation ----------------
__global__ void inv_kernel(const int* __restrict__ order) {
    int i = blockIdx.x * blockDim.x + threadIdx.x;
    if (i < 2 * QN) {
        int b = i >> 11;
        int t = i & (QN - 1);
        g_inv[(b << 11) + order[i]] = t;
    }
}

// ---------------- KNN: 1 warp / query, smem coord tiles ----------------
__global__ void knn_kernel(const float* __restrict__ qpos, const float* __restrict__ spos) {
    __shared__ float tile[1024 * 3];
    __shared__ unsigned long long cand[8][256];
    int tid = threadIdx.x, lane = tid & 31, w = tid >> 5;
    int q = blockIdx.x * 8 + w;
    float qx = qpos[q * 3 + 0], qy = qpos[q * 3 + 1], qz = qpos[q * 3 + 2];
    float qq = qx * qx + qy * qy + qz * qz;

    float bd[8]; int bi[8];
#pragma unroll
    for (int j = 0; j < 8; j++) { bd[j] = 3.4e38f; bi[j] = 0; }

    for (int base = 0; base < NP; base += 1024) {
        __syncthreads();
        for (int i = tid; i < 3072; i += 256) tile[i] = spos[base * 3 + i];
        __syncthreads();
        for (int p = lane; p < 1024; p += 32) {
            float px = tile[3 * p], py = tile[3 * p + 1], pz = tile[3 * p + 2];
            float pp = px * px + py * py + pz * pz;
            float d2 = qq + pp - 2.0f * (qx * px + qy * py + qz * pz);
            if (d2 < bd[7]) {
                bd[7] = d2; bi[7] = base + p;
#pragma unroll
                for (int j = 7; j > 0; j--) {
                    if (bd[j] < bd[j - 1]) {
                        float td = bd[j]; bd[j] = bd[j - 1]; bd[j - 1] = td;
                        int ti = bi[j]; bi[j] = bi[j - 1]; bi[j - 1] = ti;
                    }
                }
            }
        }
    }
#pragma unroll
    for (int j = 0; j < 8; j++)
        cand[w][lane * 8 + j] =
            ((unsigned long long)__float_as_uint(fmaxf(bd[j], 0.0f)) << 32) | (unsigned)bi[j];

    int head = 0;
    for (int r = 0; r < 8; r++) {
        unsigned long long key = (head < 8) ? cand[w][lane * 8 + head] : 0xFFFFFFFFFFFFFFFFull;
        unsigned long long mn = key;
#pragma unroll
        for (int off = 16; off; off >>= 1) {
            unsigned long long o = __shfl_xor_sync(0xffffffffu, mn, off);
            if (o < mn) mn = o;
        }
        if (key == mn && head < 8) head++;
        if (lane == 0) g_knn[q * 8 + r] = (int)(mn & 0xFFFFFFFFull);
    }
}

// ---------------- kw = softmax(qproj @ w_k^T + w_b) ----------------
__global__ void kw_kernel(const float* __restrict__ wk, const float* __restrict__ wb) {
    int lane = threadIdx.x & 31, w = threadIdx.x >> 5;
    int q = blockIdx.x * 8 + w;
    float qv[8];
#pragma unroll
    for (int j = 0; j < 8; j++) qv[j] = g_qproj[q * DM + j * 32 + lane];
    float lg[8];
#pragma unroll
    for (int k = 0; k < 8; k++) {
        float p = 0.0f;
#pragma unroll
        for (int j = 0; j < 8; j++) p += qv[j] * wk[k * DM + j * 32 + lane];
#pragma unroll
        for (int off = 16; off; off >>= 1) p += __shfl_xor_sync(0xffffffffu, p, off);
        lg[k] = p + wb[k];
    }
    if (lane == 0) {
        float mx = lg[0];
#pragma unroll
        for (int k = 1; k < 8; k++) mx = fmaxf(mx, lg[k]);
        float s = 0.0f;
#pragma unroll
        for (int k = 0; k < 8; k++) { lg[k] = expf(lg[k] - mx); s += lg[k]; }
        float is = 1.0f / s;
#pragma unroll
        for (int k = 0; k < 8; k++) g_kw[q * 8 + k] = lg[k] * is;
    }
}

// ---------------- mixed = sum_k kw * feat[idx] ----------------
__global__ void mix_kernel(const float* __restrict__ feats) {
    int q = blockIdx.x, d = threadIdx.x;
    float acc = 0.0f;
#pragma unroll
    for (int k = 0; k < 8; k++)
        acc += g_kw[q * 8 + k] * feats[(size_t)g_knn[q * 8 + k] * DM + d];
    g_mixed[q * DM + d] = acc;
}

__global__ void ewmul_kernel() {
    int i = blockIdx.x * blockDim.x + threadIdx.x;
    g_w[i] = g_qproj[i] * g_vm[i];
}

// ---------------- LayerNorm variants ----------------
__global__ void ln_add_kernel(float* __restrict__ out, const float* __restrict__ a,
                              const float* __restrict__ b) {
    int row = blockIdx.x, d = threadIdx.x;
    float v = a[row * DM + d] + b[row * DM + d];
    float mean = blockSum256(v) * (1.0f / DM);
    float diff = v - mean;
    float var = blockSum256(diff * diff) * (1.0f / DM);
    out[row * DM + d] = diff * rsqrtf(var + 1e-5f);
}

__global__ void ln_plain_kernel(float* __restrict__ out, const float* __restrict__ a) {
    int row = blockIdx.x, d = threadIdx.x;
    float v = a[row * DM + d];
    float mean = blockSum256(v) * (1.0f / DM);
    float diff = v - mean;
    float var = blockSum256(diff * diff) * (1.0f / DM);
    out[row * DM + d] = diff * rsqrtf(var + 1e-5f);
}

// ---------------- conv1d + silu + dt/dA precompute ----------------
__global__ void conv_dt_kernel(const float* __restrict__ Wconv, const float* __restrict__ bconv,
                               const float* __restrict__ Alog, const float* __restrict__ dtb) {
    int bt = blockIdx.x;              // 0..4095
    int b = bt >> 11, t = bt & (QN - 1);
    for (int c = threadIdx.x; c < CONVc; c += blockDim.x) {
        float acc = bconv[c];
#pragma unroll
        for (int j = 0; j < 4; j++) {
            int tt = t - 3 + j;
            if (tt >= 0)
                acc += g_proj[(size_t)(b * QN + tt) * NPROJc + DINc + c] * Wconv[c * 4 + j];
        }
        g_xBC[(size_t)bt * CONVc + c] = siluf(acc);
    }
    if (threadIdx.x < HN) {
        int h = threadIdx.x;
        float draw = g_proj[(size_t)bt * NPROJc + DINc + CONVc + h] + dtb[h];
        float dt = (draw > 20.0f) ? draw : log1pf(expf(draw));
        float A = -expf(Alog[h]);
        g_dt[bt * HN + h] = dt;
        g_dA[bt * HN + h] = expf(dt * A);
    }
}

// ---------------- sequential SSM scan: 1 warp per (b,h,d) ----------------
__global__ void scan_kernel() {
    int gw = (blockIdx.x * blockDim.x + threadIdx.x) >> 5;
    int lane = threadIdx.x & 31;
    int b = gw >> 9;
    int h = (gw >> 6) & 7;
    int d = gw & 63;
    const float* xb = g_xBC + (size_t)b * QN * CONVc;
    const float* dtp = g_dt + b * QN * HN + h;
    const float* dAp = g_dA + b * QN * HN + h;
    float* yp = g_y + (size_t)b * QN * DINc + h * HDN + d;
    int xoff = h * HDN + d;

    float h0 = 0.0f, h1 = 0.0f;
    for (int t = 0; t < QN; t += 4) {
        float c[4];
#pragma unroll
        for (int u = 0; u < 4; u++) {
            const float* row = xb + (size_t)(t + u) * CONVc;
            float da = dAp[(t + u) * HN];
            float dx = dtp[(t + u) * HN] * row[xoff];
            h0 = h0 * da + dx * row[512 + lane];
            h1 = h1 * da + dx * row[544 + lane];
            c[u] = h0 * row[576 + lane] + h1 * row[608 + lane];
        }
#pragma unroll
        for (int off = 16; off; off >>= 1) {
#pragma unroll
            for (int u = 0; u < 4; u++) c[u] += __shfl_xor_sync(0xffffffffu, c[u], off);
        }
        float v = c[0];
        if (lane == 1) v = c[1];
        else if (lane == 2) v = c[2];
        else if (lane == 3) v = c[3];
        if (lane < 4) yp[(size_t)(t + lane) * DINc] = v;
    }
}

// ---------------- gated RMSNorm: y = rms((y + D*x) * silu(z)) * rmsw ----------------
__global__ void gated_rms_kernel(const float* __restrict__ Dv, const float* __restrict__ rmsw) {
    int bt = blockIdx.x;
    int i0 = threadIdx.x, i1 = threadIdx.x + 256;
    float ga, gb;
    {
        int h = i0 >> 6;
        float yy = g_y[(size_t)bt * DINc + i0] + Dv[h] * g_xBC[(size_t)bt * CONVc + i0];
        float z = g_proj[(size_t)bt * NPROJc + i0];
        ga = yy * siluf(z);
    }
    {
        int h = i1 >> 6;
        float yy = g_y[(size_t)bt * DINc + i1] + Dv[h] * g_xBC[(size_t)bt * CONVc + i1];
        float z = g_proj[(size_t)bt * NPROJc + i1];
        gb = yy * siluf(z);
    }
    float ss = blockSum256(ga * ga + gb * gb);
    float r = rsqrtf(ss * (1.0f / DINc) + 1e-5f);
    g_y[(size_t)bt * DINc + i0] = ga * r * rmsw[i0];
    g_y[(size_t)bt * DINc + i1] = gb * r * rmsw[i1];
}

// ---------------- unsort + mean(paths) + residual + LN ----------------
__global__ void combine_ln_kernel() {
    int qi = blockIdx.x, d = threadIdx.x;
    int p0 = g_inv[qi];
    int p1 = g_inv[QN + qi];
    float v = g_x[qi * DM + d] +
              0.5f * (g_yout[(size_t)p0 * DM + d] + g_yout[(size_t)(QN + p1) * DM + d]);
    float mean = blockSum256(v) * (1.0f / DM);
    float diff = v - mean;
    float var = blockSum256(diff * diff) * (1.0f / DM);
    g_x[qi * DM + d] = diff * rsqrtf(var + 1e-5f);
}

// ---------------- FFN elementwise ----------------
__global__ void gelu_bias_kernel(const float* __restrict__ b1) {
    int i = blockIdx.x * blockDim.x + threadIdx.x;
    float v = g_h1[i] + b1[i & (HIDc - 1)];
    g_h1[i] = 0.5f * v * (1.0f + erff(v * 0.70710678118654752f));
}

__global__ void final_ln_kernel(float* __restrict__ out, const float* __restrict__ b2) {
    int row = blockIdx.x, d = threadIdx.x;
    float v = g_x[row * DM + d] + g_h2[row * DM + d] + b2[d];
    float mean = blockSum256(v) * (1.0f / DM);
    float diff = v - mean;
    float var = blockSum256(diff * diff) * (1.0f / DM);
    out[row * DM + d] = diff * rsqrtf(var + 1e-5f);
}

// ---------------- host launcher ----------------
static float* symf(const void* p) { return (float*)p; }

extern "C" void kernel_launch(void* const* d_in, const int* in_sizes, int n_in,
                              void* d_out, int out_size) {
    (void)in_sizes; (void)n_in; (void)out_size;
    const float* query     = (const float*)d_in[0];
    const float* query_pos = (const float*)d_in[1];
    const float* inst_feats= (const float*)d_in[2];
    const float* sp_coords = (const float*)d_in[3];
    const float* w_q = (const float*)d_in[4];
    const float* w_v = (const float*)d_in[5];
    const float* w_o = (const float*)d_in[6];
    const float* w_k = (const float*)d_in[7];
    const float* w_b = (const float*)d_in[8];
    const float* ssm_Win   = (const float*)d_in[9];
    const float* ssm_Wconv = (const float*)d_in[10];
    const float* ssm_bconv = (const float*)d_in[11];
    const float* ssm_Alog  = (const float*)d_in[12];
    const float* ssm_D     = (const float*)d_in[13];
    const float* ssm_dtb   = (const float*)d_in[14];
    const float* ssm_rmsw  = (const float*)d_in[15];
    const float* ssm_Wout  = (const float*)d_in[16];
    const float* ffn_w1 = (const float*)d_in[17];
    const float* ffn_b1 = (const float*)d_in[18];
    const float* ffn_w2 = (const float*)d_in[19];
    const float* ffn_b2 = (const float*)d_in[20];
    const int*   order  = (const int*)d_in[21];
    float* out = (float*)d_out;

    void *p_qproj, *p_mixed, *p_vm, *p_w, *p_tmp, *p_x, *p_xn, *p_proj, *p_y, *p_yout,
         *p_h1, *p_h2, *p_split;
    cudaGetSymbolAddress(&p_qproj, g_qproj);
    cudaGetSymbolAddress(&p_mixed, g_mixed);
    cudaGetSymbolAddress(&p_vm,    g_vm);
    cudaGetSymbolAddress(&p_w,     g_w);
    cudaGetSymbolAddress(&p_tmp,   g_tmp);
    cudaGetSymbolAddress(&p_x,     g_x);
    cudaGetSymbolAddress(&p_xn,    g_xn);
    cudaGetSymbolAddress(&p_proj,  g_proj);
    cudaGetSymbolAddress(&p_y,     g_y);
    cudaGetSymbolAddress(&p_yout,  g_yout);
    cudaGetSymbolAddress(&p_h1,    g_h1);
    cudaGetSymbolAddress(&p_h2,    g_h2);
    cudaGetSymbolAddress(&p_split, g_split);
    float* spl = symf(p_split);

    // --- front end ---
    inv_kernel<<<16, 256>>>(order);
    knn_kernel<<<QN / 8, 256>>>(query_pos, sp_coords);

    // qproj = query @ w_q^T   (2048x256x256, split-K 4)
    gemm64<<<dim3(4, 32, 4), 64>>>(query, w_q, spl, QN, DM, DM, 64, nullptr);
    reduce_split<<<QN * DM / 256, 256>>>(symf(p_qproj), spl, QN * DM, 4);
    kw_kernel<<<QN / 8, 256>>>(w_k, w_b);
    mix_kernel<<<QN, 256>>>(inst_feats);
    // vm = mixed @ w_v^T
    gemm64<<<dim3(4, 32, 4), 64>>>(symf(p_mixed), w_v, spl, QN, DM, DM, 64, nullptr);
    reduce_split<<<QN * DM / 256, 256>>>(symf(p_vm), spl, QN * DM, 4);
    ewmul_kernel<<<QN * DM / 256, 256>>>();
    // tmp = w @ w_o^T
    gemm64<<<dim3(4, 32, 4), 64>>>(symf(p_w), w_o, spl, QN, DM, DM, 64, nullptr);
    reduce_split<<<QN * DM / 256, 256>>>(symf(p_tmp), spl, QN * DM, 4);
    ln_add_kernel<<<QN, 256>>>(symf(p_x), symf(p_tmp), query);

    // --- SSM layers ---
    for (int l = 0; l < 2; l++) {
        const float* Win_l   = ssm_Win   + (size_t)l * NPROJc * DM;
        const float* Wconv_l = ssm_Wconv + (size_t)l * CONVc * 4;
        const float* bconv_l = ssm_bconv + (size_t)l * CONVc;
        const float* Alog_l  = ssm_Alog  + l * HN;
        const float* D_l     = ssm_D     + l * HN;
        const float* dtb_l   = ssm_dtb   + l * HN;
        const float* rmsw_l  = ssm_rmsw  + (size_t)l * DINc;
        const float* Wout_l  = ssm_Wout  + (size_t)l * DM * DINc;

        ln_plain_kernel<<<QN, 256>>>(symf(p_xn), symf(p_x));
        // proj = xn[order] @ Win^T  (4096x1160x256) — 19*64 = 1216 blocks, no split
        gemm64<<<dim3((NPROJc + 63) / 64, 2 * QN / 64, 1), 64>>>(
            symf(p_xn), Win_l, symf(p_proj), 2 * QN, NPROJc, DM, DM, order);
        conv_dt_kernel<<<2 * QN, 256>>>(Wconv_l, bconv_l, Alog_l, dtb_l);
        scan_kernel<<<128, 256>>>();
        gated_rms_kernel<<<2 * QN, 256>>>(D_l, rmsw_l);
        // yout = y @ Wout^T (4096x256x512, split-K 2)
        gemm64<<<dim3(4, 64, 2), 64>>>(symf(p_y), Wout_l, spl, 2 * QN, DM, DINc, 256, nullptr);
        reduce_split<<<2 * QN * DM / 256, 256>>>(symf(p_yout), spl, 2 * QN * DM, 2);
        combine_ln_kernel<<<QN, 256>>>();
    }

    // --- FFN ---
    // h1 = x @ w1^T  (2048x1024x256) — 16*32 = 512 blocks
    gemm64<<<dim3(HIDc / 64, QN / 64, 1), 64>>>(symf(p_x), ffn_w1, symf(p_h1),
                                                QN, HIDc, DM, DM, nullptr);
    gelu_bias_kernel<<<QN * HIDc / 256, 256>>>(ffn_b1);
    // h2 = h1 @ w2^T (2048x256x1024, split-K 4)
    gemm64<<<dim3(4, 32, 4), 64>>>(symf(p_h1), ffn_w2, spl, QN, DM, HIDc, 256, nullptr);
    reduce_split<<<QN * DM / 256, 256>>>(symf(p_h2), spl, QN * DM, 4);
    final_ln_kernel<<<QN, 256>>>(out, ffn_b2);
}